// round 1
// baseline (speedup 1.0000x reference)
#include <cuda_runtime.h>
#include <cstdint>

#define N_NODES 100000
#define F_IN    256
#define H_DIM   16
#define C_DIM   40

// Device-global scratch (allocation-free per harness rules)
__device__ __align__(128) float g_H1[N_NODES * H_DIM];    // x @ W1
__device__ __align__(128) float g_AGG1[N_NODES * H_DIM];  // scatter target, layer 1
__device__ __align__(128) float g_H2[N_NODES * C_DIM];    // relu(agg1+b1) @ W2
__device__ __align__(128) float g_AGG2[N_NODES * C_DIM];  // scatter target, layer 2
__device__ int g_is64;

// sm_90+ vectorized global reduction: 4 floats per L2 red op, no return value.
__device__ __forceinline__ void red_add_v4(float* addr, float a, float b, float c, float d) {
    asm volatile("red.global.add.v4.f32 [%0], {%1, %2, %3, %4};"
                 :: "l"(addr), "f"(a), "f"(b), "f"(c), "f"(d)
                 : "memory");
}

// ---------------------------------------------------------------------------
// k_detect: is edge_index int64 or int32?
// If int64 (values < 2^31, nonneg), every odd 32-bit word (hi half) is 0.
// If int32, odd words are src[1],src[3],... (uniform in [0,1e5)) — the chance
// that 512 of them are ALL zero is ~0. Reads only the first 4KB (safe for both).
// ---------------------------------------------------------------------------
__global__ void k_detect(const unsigned int* __restrict__ ei32) {
    int lane = threadIdx.x;           // 32 threads
    bool ok = true;
    #pragma unroll
    for (int i = 0; i < 16; i++) {
        int pos = 2 * (lane * 16 + i) + 1;   // odd words 1..1023
        ok &= (ei32[pos] == 0u);
    }
    bool all64 = __all_sync(0xFFFFFFFFu, ok);
    if (lane == 0) g_is64 = all64 ? 1 : 0;
}

// ---------------------------------------------------------------------------
// k_gemm1: g_H1 = x @ W1   (thread-per-node, W1 staged in smem as float4)
// Also zeroes g_AGG1 row for this node.
// ---------------------------------------------------------------------------
__global__ void k_gemm1(const float* __restrict__ x, const float* __restrict__ W1) {
    __shared__ float4 Ws[F_IN][4];     // W1 row k = 16 floats = 4 float4
    const float4* W4 = (const float4*)W1;
    for (int i = threadIdx.x; i < F_IN * 4; i += blockDim.x)
        Ws[i >> 2][i & 3] = W4[i];
    __syncthreads();

    int n = blockIdx.x * blockDim.x + threadIdx.x;
    if (n >= N_NODES) return;

    float acc[16];
    #pragma unroll
    for (int j = 0; j < 16; j++) acc[j] = 0.f;

    const float4* xr = (const float4*)(x + (size_t)n * F_IN);
    #pragma unroll 4
    for (int kk = 0; kk < F_IN / 4; kk++) {
        float4 xv = xr[kk];
        float xs[4] = {xv.x, xv.y, xv.z, xv.w};
        #pragma unroll
        for (int r = 0; r < 4; r++) {
            int k = kk * 4 + r;
            float4 w0 = Ws[k][0], w1 = Ws[k][1], w2 = Ws[k][2], w3 = Ws[k][3];
            float v = xs[r];
            acc[0]  += v * w0.x; acc[1]  += v * w0.y; acc[2]  += v * w0.z; acc[3]  += v * w0.w;
            acc[4]  += v * w1.x; acc[5]  += v * w1.y; acc[6]  += v * w1.z; acc[7]  += v * w1.w;
            acc[8]  += v * w2.x; acc[9]  += v * w2.y; acc[10] += v * w2.z; acc[11] += v * w2.w;
            acc[12] += v * w3.x; acc[13] += v * w3.y; acc[14] += v * w3.z; acc[15] += v * w3.w;
        }
    }

    float4* h = (float4*)(g_H1 + (size_t)n * H_DIM);
    h[0] = make_float4(acc[0],  acc[1],  acc[2],  acc[3]);
    h[1] = make_float4(acc[4],  acc[5],  acc[6],  acc[7]);
    h[2] = make_float4(acc[8],  acc[9],  acc[10], acc[11]);
    h[3] = make_float4(acc[12], acc[13], acc[14], acc[15]);

    float4 z = make_float4(0.f, 0.f, 0.f, 0.f);
    float4* a = (float4*)(g_AGG1 + (size_t)n * H_DIM);
    a[0] = z; a[1] = z; a[2] = z; a[3] = z;
}

// ---------------------------------------------------------------------------
// k_scatter1: per edge e: g_AGG1[dst] += g_H1[src] * ew   (4x red.v4)
// ---------------------------------------------------------------------------
__global__ void k_scatter1(const void* __restrict__ ei, const float* __restrict__ ew, int E) {
    int e = blockIdx.x * blockDim.x + threadIdx.x;
    if (e >= E) return;
    long long s, d;
    if (g_is64) {
        const long long* p = (const long long*)ei;
        s = p[e]; d = p[E + e];
    } else {
        const int* p = (const int*)ei;
        s = p[e]; d = p[E + e];
    }
    float w = ew[e];
    const float4* hp = (const float4*)(g_H1 + (size_t)s * H_DIM);
    float* ap = g_AGG1 + (size_t)d * H_DIM;
    #pragma unroll
    for (int i = 0; i < 4; i++) {
        float4 v = hp[i];
        red_add_v4(ap + i * 4, v.x * w, v.y * w, v.z * w, v.w * w);
    }
}

// ---------------------------------------------------------------------------
// k_layer2: g_H2 = relu(g_AGG1 + b1) @ W2 ; also zero g_AGG2 row
// ---------------------------------------------------------------------------
__global__ void k_layer2(const float* __restrict__ b1, const float* __restrict__ W2) {
    __shared__ float4 W2s[16][10];     // W2 row i = 40 floats = 10 float4
    __shared__ float  b1s[16];
    for (int i = threadIdx.x; i < 160; i += blockDim.x)
        W2s[i / 10][i % 10] = ((const float4*)W2)[i];
    if (threadIdx.x < 16) b1s[threadIdx.x] = b1[threadIdx.x];
    __syncthreads();

    int n = blockIdx.x * blockDim.x + threadIdx.x;
    if (n >= N_NODES) return;

    const float4* ar = (const float4*)(g_AGG1 + (size_t)n * H_DIM);
    float v[16];
    #pragma unroll
    for (int i = 0; i < 4; i++) {
        float4 t = ar[i];
        v[4*i] = t.x; v[4*i+1] = t.y; v[4*i+2] = t.z; v[4*i+3] = t.w;
    }
    #pragma unroll
    for (int i = 0; i < 16; i++) {
        float t = v[i] + b1s[i];
        v[i] = t > 0.f ? t : 0.f;
    }

    float4 out[10];
    #pragma unroll
    for (int j = 0; j < 10; j++) out[j] = make_float4(0.f, 0.f, 0.f, 0.f);
    #pragma unroll
    for (int i = 0; i < 16; i++) {
        float vi = v[i];
        #pragma unroll
        for (int j = 0; j < 10; j++) {
            float4 w = W2s[i][j];
            out[j].x += vi * w.x; out[j].y += vi * w.y;
            out[j].z += vi * w.z; out[j].w += vi * w.w;
        }
    }

    float4* hp  = (float4*)(g_H2   + (size_t)n * C_DIM);
    float4* ap2 = (float4*)(g_AGG2 + (size_t)n * C_DIM);
    float4 z = make_float4(0.f, 0.f, 0.f, 0.f);
    #pragma unroll
    for (int j = 0; j < 10; j++) { hp[j] = out[j]; ap2[j] = z; }
}

// ---------------------------------------------------------------------------
// k_scatter2: per edge e: g_AGG2[dst] += g_H2[src] * ew   (10x red.v4)
// ---------------------------------------------------------------------------
__global__ void k_scatter2(const void* __restrict__ ei, const float* __restrict__ ew, int E) {
    int e = blockIdx.x * blockDim.x + threadIdx.x;
    if (e >= E) return;
    long long s, d;
    if (g_is64) {
        const long long* p = (const long long*)ei;
        s = p[e]; d = p[E + e];
    } else {
        const int* p = (const int*)ei;
        s = p[e]; d = p[E + e];
    }
    float w = ew[e];
    const float4* hp = (const float4*)(g_H2 + (size_t)s * C_DIM);
    float* ap = g_AGG2 + (size_t)d * C_DIM;
    #pragma unroll
    for (int i = 0; i < 10; i++) {
        float4 v = hp[i];
        red_add_v4(ap + i * 4, v.x * w, v.y * w, v.z * w, v.w * w);
    }
}

// ---------------------------------------------------------------------------
// k_softmax: out = log_softmax(g_AGG2 + b2, axis=1)
// ---------------------------------------------------------------------------
__global__ void k_softmax(const float* __restrict__ b2, float* __restrict__ out) {
    __shared__ float b2s[C_DIM];
    if (threadIdx.x < C_DIM) b2s[threadIdx.x] = b2[threadIdx.x];
    __syncthreads();

    int n = blockIdx.x * blockDim.x + threadIdx.x;
    if (n >= N_NODES) return;

    float v[C_DIM];
    const float4* ar = (const float4*)(g_AGG2 + (size_t)n * C_DIM);
    #pragma unroll
    for (int i = 0; i < 10; i++) {
        float4 t = ar[i];
        v[4*i]   = t.x + b2s[4*i];
        v[4*i+1] = t.y + b2s[4*i+1];
        v[4*i+2] = t.z + b2s[4*i+2];
        v[4*i+3] = t.w + b2s[4*i+3];
    }
    float m = v[0];
    #pragma unroll
    for (int j = 1; j < C_DIM; j++) m = fmaxf(m, v[j]);
    float s = 0.f;
    #pragma unroll
    for (int j = 0; j < C_DIM; j++) s += __expf(v[j] - m);
    float ls = __logf(s);

    float4* op = (float4*)(out + (size_t)n * C_DIM);
    #pragma unroll
    for (int i = 0; i < 10; i++)
        op[i] = make_float4(v[4*i] - m - ls, v[4*i+1] - m - ls,
                            v[4*i+2] - m - ls, v[4*i+3] - m - ls);
}

// ---------------------------------------------------------------------------
extern "C" void kernel_launch(void* const* d_in, const int* in_sizes, int n_in,
                              void* d_out, int out_size) {
    const float* x  = (const float*)d_in[0];
    const void*  ei = d_in[1];                 // int64 or int32, detected on device
    const float* ew = (const float*)d_in[2];
    const float* W1 = (const float*)d_in[3];
    const float* b1 = (const float*)d_in[4];
    const float* W2 = (const float*)d_in[5];
    const float* b2 = (const float*)d_in[6];
    int E = in_sizes[2];                        // edge_weight element count

    int nb_nodes = (N_NODES + 255) / 256;
    int nb_edges = (E + 255) / 256;

    k_detect  <<<1, 32>>>((const unsigned int*)ei);
    k_gemm1   <<<nb_nodes, 256>>>(x, W1);
    k_scatter1<<<nb_edges, 256>>>(ei, ew, E);
    k_layer2  <<<nb_nodes, 256>>>(b1, W2);
    k_scatter2<<<nb_edges, 256>>>(ei, ew, E);
    k_softmax <<<nb_nodes, 256>>>(b2, (float*)d_out);
}

// round 3
// speedup vs baseline: 1.5444x; 1.5444x over previous
#include <cuda_runtime.h>
#include <cstdint>

#define N_NODES 100000
#define F_IN    256
#define H_DIM   16
#define C_DIM   40
#define E_MAX   3400000

// Device-global scratch (allocation-free per harness rules)
__device__ __align__(128) float g_H1[N_NODES * H_DIM];     // x @ W1
__device__ __align__(128) float g_AGG1[N_NODES * H_DIM];   // scatter target, layer 1
__device__ __align__(128) float g_R[N_NODES * H_DIM];      // relu(AGG1 + b1)
__device__ __align__(128) float g_AGG16[N_NODES * H_DIM];  // 16-dim scatter target, layer 2
__device__ __align__(16)  int2  g_EDGE[E_MAX];             // packed (src, dst) int32
__device__ int g_is64;

// sm_90+ vectorized global reduction: 4 floats per L2 red op, no return value.
__device__ __forceinline__ void red_add_v4(float* addr, float a, float b, float c, float d) {
    asm volatile("red.global.add.v4.f32 [%0], {%1, %2, %3, %4};"
                 :: "l"(addr), "f"(a), "f"(b), "f"(c), "f"(d)
                 : "memory");
}

// ---------------------------------------------------------------------------
// k_detect: int64 vs int32 edge_index. If int64 (values in [0,1e5)), every odd
// 32-bit word is 0. For int32 random indices the odds all 512 are zero ~ 0.
// Reads only the first 4KB (valid under either layout).
// ---------------------------------------------------------------------------
__global__ void k_detect(const unsigned int* __restrict__ ei32) {
    int lane = threadIdx.x;  // 32 threads
    bool ok = true;
    #pragma unroll
    for (int i = 0; i < 16; i++) {
        int pos = 2 * (lane * 16 + i) + 1;
        ok &= (ei32[pos] == 0u);
    }
    bool all64 = __all_sync(0xFFFFFFFFu, ok);
    if (lane == 0) g_is64 = all64 ? 1 : 0;
}

// ---------------------------------------------------------------------------
// k_convert: pack (src,dst) into int2 records; reads the index array once.
// ---------------------------------------------------------------------------
__global__ void k_convert(const void* __restrict__ ei, int E) {
    int e = blockIdx.x * blockDim.x + threadIdx.x;
    if (e >= E) return;
    int s, d;
    if (g_is64) {
        const long long* p = (const long long*)ei;
        s = (int)p[e]; d = (int)p[E + e];
    } else {
        const int* p = (const int*)ei;
        s = p[e]; d = p[E + e];
    }
    g_EDGE[e] = make_int2(s, d);
}

// ---------------------------------------------------------------------------
// k_gemm1: g_H1 = x @ W1 (thread-per-node, W1 in smem); zero g_AGG1 row.
// ---------------------------------------------------------------------------
__global__ void k_gemm1(const float* __restrict__ x, const float* __restrict__ W1) {
    __shared__ float4 Ws[F_IN][4];
    const float4* W4 = (const float4*)W1;
    for (int i = threadIdx.x; i < F_IN * 4; i += blockDim.x)
        Ws[i >> 2][i & 3] = W4[i];
    __syncthreads();

    int n = blockIdx.x * blockDim.x + threadIdx.x;
    if (n >= N_NODES) return;

    float acc[16];
    #pragma unroll
    for (int j = 0; j < 16; j++) acc[j] = 0.f;

    const float4* xr = (const float4*)(x + (size_t)n * F_IN);
    #pragma unroll 4
    for (int kk = 0; kk < F_IN / 4; kk++) {
        float4 xv = xr[kk];
        float xs[4] = {xv.x, xv.y, xv.z, xv.w};
        #pragma unroll
        for (int r = 0; r < 4; r++) {
            int k = kk * 4 + r;
            float4 w0 = Ws[k][0], w1 = Ws[k][1], w2 = Ws[k][2], w3 = Ws[k][3];
            float v = xs[r];
            acc[0]  += v * w0.x; acc[1]  += v * w0.y; acc[2]  += v * w0.z; acc[3]  += v * w0.w;
            acc[4]  += v * w1.x; acc[5]  += v * w1.y; acc[6]  += v * w1.z; acc[7]  += v * w1.w;
            acc[8]  += v * w2.x; acc[9]  += v * w2.y; acc[10] += v * w2.z; acc[11] += v * w2.w;
            acc[12] += v * w3.x; acc[13] += v * w3.y; acc[14] += v * w3.z; acc[15] += v * w3.w;
        }
    }

    float4* h = (float4*)(g_H1 + (size_t)n * H_DIM);
    h[0] = make_float4(acc[0],  acc[1],  acc[2],  acc[3]);
    h[1] = make_float4(acc[4],  acc[5],  acc[6],  acc[7]);
    h[2] = make_float4(acc[8],  acc[9],  acc[10], acc[11]);
    h[3] = make_float4(acc[12], acc[13], acc[14], acc[15]);

    float4 z = make_float4(0.f, 0.f, 0.f, 0.f);
    float4* a = (float4*)(g_AGG1 + (size_t)n * H_DIM);
    a[0] = z; a[1] = z; a[2] = z; a[3] = z;
}

// ---------------------------------------------------------------------------
// k_scatter16<PHASE>: 16-dim weighted scatter-add. PHASE=0: H1 -> AGG1,
// PHASE=1: R -> AGG16. Globals referenced in DEVICE code (host cannot pass
// __device__ symbols as arguments — that was the R2 bug).
// ---------------------------------------------------------------------------
template <int PHASE>
__global__ void k_scatter16(const float* __restrict__ ew, int E) {
    int e = blockIdx.x * blockDim.x + threadIdx.x;
    if (e >= E) return;
    const float* feat = (PHASE == 0) ? g_H1 : g_R;
    float*       agg  = (PHASE == 0) ? g_AGG1 : g_AGG16;

    int2 sd = g_EDGE[e];
    float w = __ldg(ew + e);
    const float4* hp = (const float4*)(feat + (size_t)sd.x * H_DIM);
    float* ap = agg + (size_t)sd.y * H_DIM;
    float4 v0 = hp[0], v1 = hp[1], v2 = hp[2], v3 = hp[3];
    red_add_v4(ap +  0, v0.x * w, v0.y * w, v0.z * w, v0.w * w);
    red_add_v4(ap +  4, v1.x * w, v1.y * w, v1.z * w, v1.w * w);
    red_add_v4(ap +  8, v2.x * w, v2.y * w, v2.z * w, v2.w * w);
    red_add_v4(ap + 12, v3.x * w, v3.y * w, v3.z * w, v3.w * w);
}

// ---------------------------------------------------------------------------
// k_relu: g_R = relu(g_AGG1 + b1); zero g_AGG16 row.
// ---------------------------------------------------------------------------
__global__ void k_relu(const float* __restrict__ b1) {
    __shared__ float b1s[H_DIM];
    if (threadIdx.x < H_DIM) b1s[threadIdx.x] = b1[threadIdx.x];
    __syncthreads();

    int n = blockIdx.x * blockDim.x + threadIdx.x;
    if (n >= N_NODES) return;

    const float4* ar = (const float4*)(g_AGG1 + (size_t)n * H_DIM);
    float4* rr = (float4*)(g_R + (size_t)n * H_DIM);
    float4* az = (float4*)(g_AGG16 + (size_t)n * H_DIM);
    float4 z = make_float4(0.f, 0.f, 0.f, 0.f);
    #pragma unroll
    for (int i = 0; i < 4; i++) {
        float4 t = ar[i];
        t.x = fmaxf(t.x + b1s[4*i+0], 0.f);
        t.y = fmaxf(t.y + b1s[4*i+1], 0.f);
        t.z = fmaxf(t.z + b1s[4*i+2], 0.f);
        t.w = fmaxf(t.w + b1s[4*i+3], 0.f);
        rr[i] = t;
        az[i] = z;
    }
}

// ---------------------------------------------------------------------------
// k_out: out = log_softmax(g_AGG16 @ W2 + b2, axis=1)
// (valid because scatter-add commutes with the linear map W2)
// ---------------------------------------------------------------------------
__global__ void k_out(const float* __restrict__ W2, const float* __restrict__ b2,
                      float* __restrict__ out) {
    __shared__ float4 W2s[16][10];  // W2 row i = 40 floats = 10 float4
    __shared__ float  b2s[C_DIM];
    for (int i = threadIdx.x; i < 160; i += blockDim.x)
        W2s[i / 10][i % 10] = ((const float4*)W2)[i];
    if (threadIdx.x < C_DIM) b2s[threadIdx.x] = b2[threadIdx.x];
    __syncthreads();

    int n = blockIdx.x * blockDim.x + threadIdx.x;
    if (n >= N_NODES) return;

    float v[16];
    const float4* ar = (const float4*)(g_AGG16 + (size_t)n * H_DIM);
    #pragma unroll
    for (int i = 0; i < 4; i++) {
        float4 t = ar[i];
        v[4*i] = t.x; v[4*i+1] = t.y; v[4*i+2] = t.z; v[4*i+3] = t.w;
    }

    float o[C_DIM];
    #pragma unroll
    for (int j = 0; j < C_DIM; j++) o[j] = b2s[j];
    #pragma unroll
    for (int i = 0; i < 16; i++) {
        float vi = v[i];
        #pragma unroll
        for (int j = 0; j < 10; j++) {
            float4 w = W2s[i][j];
            o[4*j+0] += vi * w.x; o[4*j+1] += vi * w.y;
            o[4*j+2] += vi * w.z; o[4*j+3] += vi * w.w;
        }
    }

    float m = o[0];
    #pragma unroll
    for (int j = 1; j < C_DIM; j++) m = fmaxf(m, o[j]);
    float s = 0.f;
    #pragma unroll
    for (int j = 0; j < C_DIM; j++) s += __expf(o[j] - m);
    float ls = __logf(s) + m;

    float4* op = (float4*)(out + (size_t)n * C_DIM);
    #pragma unroll
    for (int j = 0; j < 10; j++)
        op[j] = make_float4(o[4*j] - ls, o[4*j+1] - ls, o[4*j+2] - ls, o[4*j+3] - ls);
}

// ---------------------------------------------------------------------------
extern "C" void kernel_launch(void* const* d_in, const int* in_sizes, int n_in,
                              void* d_out, int out_size) {
    const float* x  = (const float*)d_in[0];
    const void*  ei = d_in[1];
    const float* ew = (const float*)d_in[2];
    const float* W1 = (const float*)d_in[3];
    const float* b1 = (const float*)d_in[4];
    const float* W2 = (const float*)d_in[5];
    const float* b2 = (const float*)d_in[6];
    int E = in_sizes[2];

    int nb_nodes = (N_NODES + 255) / 256;
    int nb_edges = (E + 255) / 256;

    k_detect      <<<1, 32>>>((const unsigned int*)ei);
    k_convert     <<<nb_edges, 256>>>(ei, E);
    k_gemm1       <<<nb_nodes, 256>>>(x, W1);
    k_scatter16<0><<<nb_edges, 256>>>(ew, E);
    k_relu        <<<nb_nodes, 256>>>(b1);
    k_scatter16<1><<<nb_edges, 256>>>(ew, E);
    k_out         <<<nb_nodes, 256>>>(W2, b2, (float*)d_out);
}